// round 12
// baseline (speedup 1.0000x reference)
#include <cuda_runtime.h>

#define CCH 512
#define HH 192
#define WW 192
#define LL 36864
#define KK 64
#define EPSF 1e-12f

typedef unsigned long long u64;
typedef unsigned int u32;

// ---------------- static scratch (no allocations allowed) ----------------
__device__ float g_invn[LL];
__device__ float g_soft[KK*LL];
__device__ u64   g_mask[LL];
__device__ float g_sa2[KK*LL];   // pre-scaled: weight * invn
__device__ float g_S[KK];
__device__ float g_vlad[KK*CCH];
__device__ float g_gsq;

// ---------------- f32x2 helpers ----------------
__device__ __forceinline__ void ffma2(u64& d, u64 a, u64 b){
    asm("fma.rn.f32x2 %0, %1, %2, %0;" : "+l"(d) : "l"(a), "l"(b));
}
__device__ __forceinline__ u64 pack2(float a, float b){
    u64 r; asm("mov.b64 %0, {%1, %2};" : "=l"(r) : "f"(a), "f"(b)); return r;
}
__device__ __forceinline__ float lo2(u64 v){ return __uint_as_float((u32)v); }
__device__ __forceinline__ float hi2(u64 v){ return __uint_as_float((u32)(v >> 32)); }

// ---------------- cp.async helpers ----------------
__device__ __forceinline__ void cpa8(void* dst, const void* src){
    u32 d = (u32)__cvta_generic_to_shared(dst);
    asm volatile("cp.async.ca.shared.global [%0], [%1], 8;" :: "r"(d), "l"(src));
}
__device__ __forceinline__ void cpa_commit(){
    asm volatile("cp.async.commit_group;");
}
template<int N>
__device__ __forceinline__ void cpa_wait(){
    asm volatile("cp.async.wait_group %0;" :: "n"(N));
}

// ---------------- K0: zero accumulators ----------------
__global__ void k_zero(){
    int i = blockIdx.x*256 + threadIdx.x;
    if (i < KK*CCH) g_vlad[i] = 0.f;
    if (i < KK)     g_S[i]    = 0.f;
    if (i == 0)     g_gsq     = 0.f;
}

// ---------------- K1: GEMM1 (f32x2, reg double-buffered) + invn + softmax + top2 ----------------
// Block: 256 threads, 64 k x 128 pixels. C in chunks of 16 (8 c-pairs). (R8 proven)
__global__ __launch_bounds__(256) void k_logits(const float* __restrict__ x,
                                                const float* __restrict__ cw){
    __shared__ __align__(16) float lsm[KK*128];          // 32KB; tiles aliased at front
    __shared__ float invs[128], mxs[128], rss[128], ssqs[256];
    u64* Wsu  = (u64*)lsm;              // [64][8]  c-pairs (natural from conv_w)
    u64* Xspu = (u64*)lsm + 512;        // [8][130] pair-major: (cpair, pixel)

    const int tid  = threadIdx.x;
    const int pix0 = blockIdx.x * 128;
    const int tl   = tid & 31;          // pixel lane: l = tl + 32*ll
    const int tkq  = tid >> 5;          // k group:  k = tkq*8 + kk (warp-uniform)
    const int lp   = tid & 127;         // loader pixel
    const int lj   = tid >> 7;          // loader cpair base (0/1); jp = lj + 2*s

    u64 acc[8][4];
    #pragma unroll
    for (int a = 0; a < 8; a++)
        #pragma unroll
        for (int b = 0; b < 4; b++) acc[a][b] = 0ull;

    float ssq = 0.f;

    u64   pW[2];
    float pX0[4], pX1[4];

    // prefetch chunk 0
    {
        #pragma unroll
        for (int s = 0; s < 2; s++){
            int i = tid + s*256;
            pW[s] = ((const u64*)cw)[(i>>3)*(CCH/2) + (i&7)];
        }
        #pragma unroll
        for (int s = 0; s < 4; s++){
            int jp = lj + 2*s;
            pX0[s] = x[(2*jp    )*LL + pix0 + lp];
            pX1[s] = x[(2*jp + 1)*LL + pix0 + lp];
        }
    }

    for (int c0 = 0; c0 < CCH; c0 += 16){
        __syncthreads();    // previous compute done -> smem reusable
        #pragma unroll
        for (int s = 0; s < 2; s++) Wsu[tid + s*256] = pW[s];
        #pragma unroll
        for (int s = 0; s < 4; s++){
            int jp = lj + 2*s;
            ssq += pX0[s]*pX0[s] + pX1[s]*pX1[s];
            Xspu[jp*130 + lp] = pack2(pX0[s], pX1[s]);
        }
        __syncthreads();
        if (c0 + 16 < CCH){
            int cn = c0 + 16;
            #pragma unroll
            for (int s = 0; s < 2; s++){
                int i = tid + s*256;
                pW[s] = ((const u64*)cw)[(i>>3)*(CCH/2) + (cn>>1) + (i&7)];
            }
            #pragma unroll
            for (int s = 0; s < 4; s++){
                int jp = lj + 2*s;
                pX0[s] = x[(cn + 2*jp    )*LL + pix0 + lp];
                pX1[s] = x[(cn + 2*jp + 1)*LL + pix0 + lp];
            }
        }
        #pragma unroll
        for (int jp = 0; jp < 8; jp++){
            u64 xv[4];
            #pragma unroll
            for (int ll = 0; ll < 4; ll++) xv[ll] = Xspu[jp*130 + tl + 32*ll];
            #pragma unroll
            for (int kk = 0; kk < 8; kk++){
                u64 w = Wsu[(tkq*8 + kk)*8 + jp];
                #pragma unroll
                for (int ll = 0; ll < 4; ll++) ffma2(acc[kk][ll], w, xv[ll]);
            }
        }
    }

    // per-pixel 1/norm
    __syncthreads();
    ssqs[tid] = ssq;
    __syncthreads();
    if (tid < 128){
        float s = ssqs[tid] + ssqs[tid + 128];
        float iv = 1.f / fmaxf(sqrtf(s), EPSF);
        invs[tid] = iv;
        g_invn[pix0 + tid] = iv;
    }
    __syncthreads();

    // scaled logits -> smem
    #pragma unroll
    for (int kk = 0; kk < 8; kk++)
        #pragma unroll
        for (int ll = 0; ll < 4; ll++){
            int l = tl + 32*ll;
            lsm[(tkq*8 + kk)*128 + l] = (lo2(acc[kk][ll]) + hi2(acc[kk][ll])) * invs[l];
        }
    __syncthreads();

    // per-pixel softmax stats + top-2 mask
    if (tid < 128){
        float v1 = -1e30f, v2 = -1e30f;
        int i1 = 0, i2 = 0;
        #pragma unroll
        for (int k = 0; k < KK; k++){
            float v = lsm[k*128 + tid];
            if (v > v1){ v2 = v1; i2 = i1; v1 = v; i1 = k; }
            else if (v > v2){ v2 = v; i2 = k; }
        }
        float s = 0.f;
        #pragma unroll
        for (int k = 0; k < KK; k++) s += __expf(lsm[k*128 + tid] - v1);
        mxs[tid] = v1;
        rss[tid] = 1.f / s;
        g_mask[pix0 + tid] = (1ull << i1) | (1ull << i2);
    }
    __syncthreads();

    for (int i = tid; i < KK*128; i += 256){
        int k = i >> 7, p = i & 127;
        g_soft[k*LL + pix0 + p] = __expf(lsm[i] - mxs[p]) * rss[p];
    }
}

// ---------------- K2: neighbor-count weight (CSA popcount) + fused S[k] ----------------
__device__ __forceinline__ void fa(u64 a, u64 b, u64 c, u64& s, u64& cy){
    u64 t = a ^ b; s = t ^ c; cy = (a & b) | (c & t);
}

__global__ __launch_bounds__(256) void k_weight(){
    const int p  = blockIdx.x*256 + threadIdx.x;
    const int k0 = blockIdx.y*16;
    __shared__ float ssm[16];
    if (threadIdx.x < 16) ssm[threadIdx.x] = 0.f;
    __syncthreads();

    const int i = p / WW, j = p % WW;
    u64 m[9];
    int t = 0;
    #pragma unroll
    for (int di = -1; di <= 1; di++)
        #pragma unroll
        for (int dj = -1; dj <= 1; dj++){
            int ii = i + di, jj = j + dj;
            m[t++] = (ii >= 0 && ii < HH && jj >= 0 && jj < WW) ? g_mask[ii*WW + jj] : 0ull;
        }
    u64 s1,c1,s2,c2,s3,c3,s4,c4,s5,c5;
    fa(m[0],m[1],m[2],s1,c1);
    fa(m[3],m[4],m[5],s2,c2);
    fa(m[6],m[7],m[8],s3,c3);
    fa(s1,s2,s3,s4,c4);
    fa(c1,c2,c3,s5,c5);
    u64 b0 = s4;
    u64 b1 = s5 ^ c4;
    u64 u  = s5 & c4;
    u64 b2 = c5 ^ u;
    u64 b3 = c5 & u;

    int mi = min(i, HH-1-i), mj = min(j, WW-1-j);
    float mf = (float)min(mi, mj);
    float m2 = mf*mf;
    float poly = m2*m2;
    float ivp  = g_invn[p];

    #pragma unroll
    for (int kk = 0; kk < 16; kk++){
        int k = k0 + kk;
        int cnt = (int)((b0>>k)&1) + 2*(int)((b1>>k)&1)
                + 4*(int)((b2>>k)&1) + 8*(int)((b3>>k)&1);
        float v = g_soft[k*LL + p] * (float)cnt * poly;
        g_sa2[k*LL + p] = v * ivp;
        #pragma unroll
        for (int o = 16; o > 0; o >>= 1) v += __shfl_xor_sync(0xffffffffu, v, o);
        if ((threadIdx.x & 31) == 0) atomicAdd(&ssm[kk], v);
    }
    __syncthreads();
    if (threadIdx.x < 16) atomicAdd(&g_S[k0 + threadIdx.x], ssm[threadIdx.x]);
}

// ---------------- K3: GEMM2 (f32x2, cp.async 3-stage, 1 barrier/chunk) ----------------
// vlad[k,c] += sum_l sa2'[k,l]*x[c,l]. Tile 64k x 128c, L-chunk 256/block, grid (144,4).
// Per-thread 4k x 8c. Dynamic smem: 3 stages x (A 64x17 + B 16x130) u64 = 76032 B.
#define APITCH 17
#define ASTG   (64*APITCH)     // 1088 u64
#define BPITCH 130
#define BSTG   (16*BPITCH)     // 2080 u64
#define STGU   (ASTG + BSTG)   // 3168 u64 per stage

__global__ __launch_bounds__(256) void k_vlad(const float* __restrict__ x){
    extern __shared__ u64 smv[];           // [3][STGU]
    const int tid = threadIdx.x;
    const int l0  = blockIdx.x * 256;
    const int c0  = blockIdx.y * 128;
    const int tc  = tid & 15;      // c = c0 + tc + 16*cc, cc 0..7
    const int tk  = tid >> 4;      // k = tk + 16*kk, kk 0..3
    const int sr  = tid >> 4;      // staging row piece
    const int sq  = tid & 15;      // staging qp

    u64 acc[4][8];
    #pragma unroll
    for (int a = 0; a < 4; a++)
        #pragma unroll
        for (int b = 0; b < 8; b++) acc[a][b] = 0ull;

    // stage chunks 0 and 1
    #pragma unroll
    for (int pc = 0; pc < 2; pc++){
        u64* As = smv + pc*STGU;
        u64* Bs = As + ASTG;
        const int lb = l0 + pc*32;
        #pragma unroll
        for (int jj = 0; jj < 4; jj++){
            int r = sr + jj*16;
            cpa8(&As[r*APITCH + sq], (const u64*)(g_sa2 + r*LL + lb) + sq);
        }
        #pragma unroll
        for (int jj = 0; jj < 8; jj++){
            int cc = sr + jj*16;
            cpa8(&Bs[sq*BPITCH + cc], (const u64*)(x + (c0+cc)*LL + lb) + sq);
        }
        cpa_commit();
    }

    int cur = 0;
    #pragma unroll 1
    for (int ch = 0; ch < 8; ch++){
        if (ch < 7) cpa_wait<1>(); else cpa_wait<0>();
        __syncthreads();           // chunk ch visible to all; also fences buf reuse
        u64* As = smv + cur*STGU;
        u64* Bs = As + ASTG;
        // stage chunk ch+2 into buffer (cur+2)%3 (computed at iter ch-1; safe)
        if (ch < 6){
            int nxt = cur + 2; if (nxt >= 3) nxt -= 3;
            u64* Asn = smv + nxt*STGU;
            u64* Bsn = Asn + ASTG;
            const int lb = l0 + (ch+2)*32;
            #pragma unroll
            for (int jj = 0; jj < 4; jj++){
                int r = sr + jj*16;
                cpa8(&Asn[r*APITCH + sq], (const u64*)(g_sa2 + r*LL + lb) + sq);
            }
            #pragma unroll
            for (int jj = 0; jj < 8; jj++){
                int cc = sr + jj*16;
                cpa8(&Bsn[sq*BPITCH + cc], (const u64*)(x + (c0+cc)*LL + lb) + sq);
            }
            cpa_commit();
        }
        // compute chunk ch
        #pragma unroll
        for (int qp = 0; qp < 16; qp++){
            u64 bv[8];
            #pragma unroll
            for (int cc = 0; cc < 8; cc++) bv[cc] = Bs[qp*BPITCH + tc + 16*cc];
            #pragma unroll
            for (int kk = 0; kk < 4; kk++){
                u64 a = As[(tk + 16*kk)*APITCH + qp];
                #pragma unroll
                for (int cc = 0; cc < 8; cc++) ffma2(acc[kk][cc], a, bv[cc]);
            }
        }
        cur++; if (cur >= 3) cur = 0;
    }
    #pragma unroll
    for (int kk = 0; kk < 4; kk++){
        int k = tk + 16*kk;
        #pragma unroll
        for (int cc = 0; cc < 8; cc++)
            atomicAdd(&g_vlad[k*CCH + c0 + tc + 16*cc],
                      lo2(acc[kk][cc]) + hi2(acc[kk][cc]));
    }
}

// ---------------- K4: centroid subtract + row L2 + global ssq ----------------
__global__ __launch_bounds__(256) void k_rownorm(const float* __restrict__ cent,
                                                 float* __restrict__ out){
    __shared__ float red[256];
    __shared__ float vsm[CCH];
    int k = blockIdx.x;
    float S = g_S[k];
    float s = 0.f;
    for (int c = threadIdx.x; c < CCH; c += 256){
        float v = g_vlad[k*CCH + c] - S * cent[k*CCH + c];
        vsm[c] = v;
        s += v*v;
    }
    red[threadIdx.x] = s;
    __syncthreads();
    for (int o = 128; o > 0; o >>= 1){
        if (threadIdx.x < o) red[threadIdx.x] += red[threadIdx.x + o];
        __syncthreads();
    }
    float rn = 1.f / fmaxf(sqrtf(red[0]), EPSF);
    for (int c = threadIdx.x; c < CCH; c += 256)
        out[k*CCH + c] = vsm[c] * rn;
    if (threadIdx.x == 0)
        atomicAdd(&g_gsq, red[0] * rn * rn);
}

// ---------------- K5: global L2 normalize ----------------
__global__ void k_gnorm(float* __restrict__ out){
    int i = blockIdx.x*256 + threadIdx.x;
    float r = 1.f / fmaxf(sqrtf(g_gsq), EPSF);
    out[i] *= r;
}

// ---------------- launch ----------------
extern "C" void kernel_launch(void* const* d_in, const int* in_sizes, int n_in,
                              void* d_out, int out_size){
    const float* x    = (const float*)d_in[0];   // [512, 192, 192]
    const float* cw   = (const float*)d_in[1];   // [64, 512]
    const float* cent = (const float*)d_in[2];   // [64, 512]
    float* out = (float*)d_out;                  // [64*512]
    (void)in_sizes; (void)n_in; (void)out_size;

    const int vsmem = 3 * STGU * 8;   // 76032 bytes
    cudaFuncSetAttribute(k_vlad, cudaFuncAttributeMaxDynamicSharedMemorySize, vsmem);

    k_zero   <<<128, 256>>>();
    k_logits <<<LL/128, 256>>>(x, cw);
    k_weight <<<dim3(LL/256, 4), 256>>>();
    k_vlad   <<<dim3(144, 4), 256, vsmem>>>(x);
    k_rownorm<<<KK, 256>>>(cent, out);
    k_gnorm  <<<KK*CCH/256, 256>>>(out);
}

// round 15
// speedup vs baseline: 1.0139x; 1.0139x over previous
#include <cuda_runtime.h>

#define CCH 512
#define HH 192
#define WW 192
#define LL 36864
#define KK 64
#define EPSF 1e-12f

typedef unsigned long long u64;
typedef unsigned int u32;

// ---------------- static scratch (no allocations allowed) ----------------
__device__ float g_invn[LL];
__device__ float g_soft[KK*LL];
__device__ u64   g_mask[LL];
__device__ float g_sa2[KK*LL];   // pre-scaled: weight * invn
__device__ float g_S[KK];
__device__ float g_vlad[KK*CCH];
__device__ float g_gsq;

// ---------------- f32x2 helpers ----------------
__device__ __forceinline__ void ffma2(u64& d, u64 a, u64 b){
    asm("fma.rn.f32x2 %0, %1, %2, %0;" : "+l"(d) : "l"(a), "l"(b));
}
__device__ __forceinline__ u64 pack2(float a, float b){
    u64 r; asm("mov.b64 %0, {%1, %2};" : "=l"(r) : "f"(a), "f"(b)); return r;
}
__device__ __forceinline__ float lo2(u64 v){ return __uint_as_float((u32)v); }
__device__ __forceinline__ float hi2(u64 v){ return __uint_as_float((u32)(v >> 32)); }

// ---------------- cp.async helpers ----------------
__device__ __forceinline__ void cpa8(void* dst, const void* src){
    u32 d = (u32)__cvta_generic_to_shared(dst);
    asm volatile("cp.async.ca.shared.global [%0], [%1], 8;" :: "r"(d), "l"(src));
}
__device__ __forceinline__ void cpa_commit(){
    asm volatile("cp.async.commit_group;");
}
template<int N>
__device__ __forceinline__ void cpa_wait(){
    asm volatile("cp.async.wait_group %0;" :: "n"(N));
}

// ---------------- K0: zero accumulators ----------------
__global__ void k_zero(){
    int i = blockIdx.x*256 + threadIdx.x;
    if (i < KK*CCH) g_vlad[i] = 0.f;
    if (i < KK)     g_S[i]    = 0.f;
    if (i == 0)     g_gsq     = 0.f;
}

// ---------------- K1: GEMM1 (f32x2, reg double-buffered) + invn + softmax + top2 ----------------
// Block: 256 threads, 64 k x 128 pixels. C in chunks of 16 (8 c-pairs).
// Epilogue: 256-thread split scan, exp computed once (written back to lsm).
__global__ __launch_bounds__(256) void k_logits(const float* __restrict__ x,
                                                const float* __restrict__ cw){
    __shared__ __align__(16) float lsm[KK*128];          // 32KB; tiles aliased at front
    __shared__ float invs[128], mxs[128], rss[128], ssqs[256];
    __shared__ float sv1[256], sv2[256], psum[256];
    __shared__ int   si1[256], si2[256];
    u64* Wsu  = (u64*)lsm;              // [64][8]  c-pairs (natural from conv_w)
    u64* Xspu = (u64*)lsm + 512;        // [8][130] pair-major: (cpair, pixel)

    const int tid  = threadIdx.x;
    const int pix0 = blockIdx.x * 128;
    const int tl   = tid & 31;          // pixel lane: l = tl + 32*ll
    const int tkq  = tid >> 5;          // k group:  k = tkq*8 + kk (warp-uniform)
    const int lp   = tid & 127;         // loader pixel
    const int lj   = tid >> 7;          // loader cpair base (0/1); jp = lj + 2*s

    u64 acc[8][4];
    #pragma unroll
    for (int a = 0; a < 8; a++)
        #pragma unroll
        for (int b = 0; b < 4; b++) acc[a][b] = 0ull;

    float ssq = 0.f;

    u64   pW[2];
    float pX0[4], pX1[4];

    // prefetch chunk 0
    {
        #pragma unroll
        for (int s = 0; s < 2; s++){
            int i = tid + s*256;
            pW[s] = ((const u64*)cw)[(i>>3)*(CCH/2) + (i&7)];
        }
        #pragma unroll
        for (int s = 0; s < 4; s++){
            int jp = lj + 2*s;
            pX0[s] = x[(2*jp    )*LL + pix0 + lp];
            pX1[s] = x[(2*jp + 1)*LL + pix0 + lp];
        }
    }

    for (int c0 = 0; c0 < CCH; c0 += 16){
        __syncthreads();    // previous compute done -> smem reusable
        #pragma unroll
        for (int s = 0; s < 2; s++) Wsu[tid + s*256] = pW[s];
        #pragma unroll
        for (int s = 0; s < 4; s++){
            int jp = lj + 2*s;
            ssq += pX0[s]*pX0[s] + pX1[s]*pX1[s];
            Xspu[jp*130 + lp] = pack2(pX0[s], pX1[s]);
        }
        __syncthreads();
        if (c0 + 16 < CCH){
            int cn = c0 + 16;
            #pragma unroll
            for (int s = 0; s < 2; s++){
                int i = tid + s*256;
                pW[s] = ((const u64*)cw)[(i>>3)*(CCH/2) + (cn>>1) + (i&7)];
            }
            #pragma unroll
            for (int s = 0; s < 4; s++){
                int jp = lj + 2*s;
                pX0[s] = x[(cn + 2*jp    )*LL + pix0 + lp];
                pX1[s] = x[(cn + 2*jp + 1)*LL + pix0 + lp];
            }
        }
        #pragma unroll
        for (int jp = 0; jp < 8; jp++){
            u64 xv[4];
            #pragma unroll
            for (int ll = 0; ll < 4; ll++) xv[ll] = Xspu[jp*130 + tl + 32*ll];
            #pragma unroll
            for (int kk = 0; kk < 8; kk++){
                u64 w = Wsu[(tkq*8 + kk)*8 + jp];
                #pragma unroll
                for (int ll = 0; ll < 4; ll++) ffma2(acc[kk][ll], w, xv[ll]);
            }
        }
    }

    // per-pixel 1/norm
    __syncthreads();
    ssqs[tid] = ssq;
    __syncthreads();
    if (tid < 128){
        float s = ssqs[tid] + ssqs[tid + 128];
        float iv = 1.f / fmaxf(sqrtf(s), EPSF);
        invs[tid] = iv;
        g_invn[pix0 + tid] = iv;
    }
    __syncthreads();

    // scaled logits -> smem
    #pragma unroll
    for (int kk = 0; kk < 8; kk++)
        #pragma unroll
        for (int ll = 0; ll < 4; ll++){
            int l = tl + 32*ll;
            lsm[(tkq*8 + kk)*128 + l] = (lo2(acc[kk][ll]) + hi2(acc[kk][ll])) * invs[l];
        }
    __syncthreads();

    // ---- epilogue phase 1: split top-2 scan (256 threads; pixel p, half h) ----
    {
        const int p = tid & 127, h = tid >> 7;
        const int kb = h * 32;
        float v1 = -1e30f, v2 = -1e30f;
        int i1 = kb, i2 = kb;
        #pragma unroll
        for (int kk = 0; kk < 32; kk++){
            int k = kb + kk;
            float v = lsm[k*128 + p];
            if (v > v1){ v2 = v1; i2 = i1; v1 = v; i1 = k; }
            else if (v > v2){ v2 = v; i2 = k; }
        }
        sv1[tid] = v1; sv2[tid] = v2; si1[tid] = i1; si2[tid] = i2;
    }
    __syncthreads();
    // ---- phase 2: merge halves (first-occurrence tie order == reference) ----
    if (tid < 128){
        float v1a = sv1[tid],     v2a = sv2[tid];
        int   i1a = si1[tid],     i2a = si2[tid];
        float v1b = sv1[tid+128], v2b = sv2[tid+128];
        int   i1b = si1[tid+128], i2b = si2[tid+128];
        float m1; int j1, j2;
        if (v1a >= v1b){
            m1 = v1a; j1 = i1a;
            if (v2a >= v1b){ j2 = i2a; }
            else           { j2 = i1b; }
        } else {
            m1 = v1b; j1 = i1b;
            if (v1a >= v2b){ j2 = i1a; }
            else           { j2 = i2b; }
        }
        mxs[tid] = m1;
        g_mask[pix0 + tid] = (1ull << j1) | (1ull << j2);
    }
    __syncthreads();
    // ---- phase 3: exp once, write back, partial sums ----
    {
        const int p = tid & 127, h = tid >> 7;
        const int kb = h * 32;
        float mx = mxs[p];
        float s = 0.f;
        #pragma unroll
        for (int kk = 0; kk < 32; kk++){
            int k = kb + kk;
            float e = __expf(lsm[k*128 + p] - mx);
            lsm[k*128 + p] = e;
            s += e;
        }
        psum[tid] = s;
    }
    __syncthreads();
    if (tid < 128) rss[tid] = 1.f / (psum[tid] + psum[tid + 128]);
    __syncthreads();
    // ---- phase 4: scaled store (no expf) ----
    for (int i = tid; i < KK*128; i += 256){
        int k = i >> 7, p = i & 127;
        g_soft[k*LL + pix0 + p] = lsm[i] * rss[p];
    }
}

// ---------------- K2: neighbor-count weight (CSA popcount) + fused S[k] ----------------
__device__ __forceinline__ void fa(u64 a, u64 b, u64 c, u64& s, u64& cy){
    u64 t = a ^ b; s = t ^ c; cy = (a & b) | (c & t);
}

__global__ __launch_bounds__(256) void k_weight(){
    const int p  = blockIdx.x*256 + threadIdx.x;
    const int k0 = blockIdx.y*16;
    __shared__ float ssm[16];
    if (threadIdx.x < 16) ssm[threadIdx.x] = 0.f;
    __syncthreads();

    const int i = p / WW, j = p % WW;
    u64 m[9];
    int t = 0;
    #pragma unroll
    for (int di = -1; di <= 1; di++)
        #pragma unroll
        for (int dj = -1; dj <= 1; dj++){
            int ii = i + di, jj = j + dj;
            m[t++] = (ii >= 0 && ii < HH && jj >= 0 && jj < WW) ? g_mask[ii*WW + jj] : 0ull;
        }
    u64 s1,c1,s2,c2,s3,c3,s4,c4,s5,c5;
    fa(m[0],m[1],m[2],s1,c1);
    fa(m[3],m[4],m[5],s2,c2);
    fa(m[6],m[7],m[8],s3,c3);
    fa(s1,s2,s3,s4,c4);
    fa(c1,c2,c3,s5,c5);
    u64 b0 = s4;
    u64 b1 = s5 ^ c4;
    u64 u  = s5 & c4;
    u64 b2 = c5 ^ u;
    u64 b3 = c5 & u;

    int mi = min(i, HH-1-i), mj = min(j, WW-1-j);
    float mf = (float)min(mi, mj);
    float m2 = mf*mf;
    float poly = m2*m2;
    float ivp  = g_invn[p];

    #pragma unroll
    for (int kk = 0; kk < 16; kk++){
        int k = k0 + kk;
        int cnt = (int)((b0>>k)&1) + 2*(int)((b1>>k)&1)
                + 4*(int)((b2>>k)&1) + 8*(int)((b3>>k)&1);
        float v = g_soft[k*LL + p] * (float)cnt * poly;
        g_sa2[k*LL + p] = v * ivp;
        #pragma unroll
        for (int o = 16; o > 0; o >>= 1) v += __shfl_xor_sync(0xffffffffu, v, o);
        if ((threadIdx.x & 31) == 0) atomicAdd(&ssm[kk], v);
    }
    __syncthreads();
    if (threadIdx.x < 16) atomicAdd(&g_S[k0 + threadIdx.x], ssm[threadIdx.x]);
}

// ---------------- K3: GEMM2 (f32x2, cp.async 2-stage, 64k x 128c tile) — R10 proven ----------------
// vlad[k,c] += sum_l sa2'[k,l]*x[c,l]. L-chunk 256/block, grid (144,4).
__global__ __launch_bounds__(256) void k_vlad(const float* __restrict__ x){
    __shared__ u64 Asu[2][64*17];     // sa2' pairs [k][qp], pitch 17
    __shared__ u64 Bsu[2][16*130];    // x    pairs [qp][cc], cc 0..127, pitch 130
    const int tid = threadIdx.x;
    const int l0  = blockIdx.x * 256;
    const int c0  = blockIdx.y * 128;
    const int tc  = tid & 15;      // c = c0 + tc + 16*cc, cc 0..7
    const int tk  = tid >> 4;      // k = tk + 16*kk, kk 0..3
    const int sr  = tid >> 4;      // staging row piece
    const int sq  = tid & 15;      // staging qp

    u64 acc[4][8];
    #pragma unroll
    for (int a = 0; a < 4; a++)
        #pragma unroll
        for (int b = 0; b < 8; b++) acc[a][b] = 0ull;

    // stage chunk 0 into buf 0
    {
        #pragma unroll
        for (int jj = 0; jj < 4; jj++){
            int r = sr + jj*16;
            cpa8(&Asu[0][r*17 + sq], (const u64*)(g_sa2 + r*LL + l0) + sq);
        }
        #pragma unroll
        for (int jj = 0; jj < 8; jj++){
            int cc = sr + jj*16;
            cpa8(&Bsu[0][sq*130 + cc], (const u64*)(x + (c0+cc)*LL + l0) + sq);
        }
        cpa_commit();
    }

    for (int ch = 0; ch < 8; ch++){
        const int b = ch & 1;
        if (ch < 7){
            const int lb = l0 + (ch+1)*32;
            const int nb = b ^ 1;
            #pragma unroll
            for (int jj = 0; jj < 4; jj++){
                int r = sr + jj*16;
                cpa8(&Asu[nb][r*17 + sq], (const u64*)(g_sa2 + r*LL + lb) + sq);
            }
            #pragma unroll
            for (int jj = 0; jj < 8; jj++){
                int cc = sr + jj*16;
                cpa8(&Bsu[nb][sq*130 + cc], (const u64*)(x + (c0+cc)*LL + lb) + sq);
            }
            cpa_commit();
            cpa_wait<1>();     // chunk ch landed
        } else {
            cpa_wait<0>();
        }
        __syncthreads();
        #pragma unroll
        for (int qp = 0; qp < 16; qp++){
            u64 bv[8];
            #pragma unroll
            for (int cc = 0; cc < 8; cc++) bv[cc] = Bsu[b][qp*130 + tc + 16*cc];
            #pragma unroll
            for (int kk = 0; kk < 4; kk++){
                u64 a = Asu[b][(tk + 16*kk)*17 + qp];
                #pragma unroll
                for (int cc = 0; cc < 8; cc++) ffma2(acc[kk][cc], a, bv[cc]);
            }
        }
        __syncthreads();       // compute(ch) done before buf b re-staged at ch+1
    }
    #pragma unroll
    for (int kk = 0; kk < 4; kk++){
        int k = tk + 16*kk;
        #pragma unroll
        for (int cc = 0; cc < 8; cc++)
            atomicAdd(&g_vlad[k*CCH + c0 + tc + 16*cc],
                      lo2(acc[kk][cc]) + hi2(acc[kk][cc]));
    }
}

// ---------------- K4: centroid subtract + row L2 + global ssq ----------------
__global__ __launch_bounds__(256) void k_rownorm(const float* __restrict__ cent,
                                                 float* __restrict__ out){
    __shared__ float red[256];
    __shared__ float vsm[CCH];
    int k = blockIdx.x;
    float S = g_S[k];
    float s = 0.f;
    for (int c = threadIdx.x; c < CCH; c += 256){
        float v = g_vlad[k*CCH + c] - S * cent[k*CCH + c];
        vsm[c] = v;
        s += v*v;
    }
    red[threadIdx.x] = s;
    __syncthreads();
    for (int o = 128; o > 0; o >>= 1){
        if (threadIdx.x < o) red[threadIdx.x] += red[threadIdx.x + o];
        __syncthreads();
    }
    float rn = 1.f / fmaxf(sqrtf(red[0]), EPSF);
    for (int c = threadIdx.x; c < CCH; c += 256)
        out[k*CCH + c] = vsm[c] * rn;
    if (threadIdx.x == 0)
        atomicAdd(&g_gsq, red[0] * rn * rn);
}

// ---------------- K5: global L2 normalize ----------------
__global__ void k_gnorm(float* __restrict__ out){
    int i = blockIdx.x*256 + threadIdx.x;
    float r = 1.f / fmaxf(sqrtf(g_gsq), EPSF);
    out[i] *= r;
}

// ---------------- launch ----------------
extern "C" void kernel_launch(void* const* d_in, const int* in_sizes, int n_in,
                              void* d_out, int out_size){
    const float* x    = (const float*)d_in[0];   // [512, 192, 192]
    const float* cw   = (const float*)d_in[1];   // [64, 512]
    const float* cent = (const float*)d_in[2];   // [64, 512]
    float* out = (float*)d_out;                  // [64*512]
    (void)in_sizes; (void)n_in; (void)out_size;

    k_zero   <<<128, 256>>>();
    k_logits <<<LL/128, 256>>>(x, cw);
    k_weight <<<dim3(LL/256, 4), 256>>>();
    k_vlad   <<<dim3(144, 4), 256>>>(x);
    k_rownorm<<<KK, 256>>>(cent, out);
    k_gnorm  <<<KK*CCH/256, 256>>>(out);
}